// round 2
// baseline (speedup 1.0000x reference)
#include <cuda_runtime.h>
#include <cstdint>
#include <cstddef>

// GRU: T=1024, B=64, I=512, H=512
#define Tn 1024
#define Bn 64
#define In 512
#define Hn 512
#define JB 4          // hidden units per block (scan)
#define HPAD 516      // padded h row (odd multiple of 4 floats -> conflict-free f4 LDS)
#define NBLK 128      // scan blocks (<= #SMs, all co-resident)

typedef unsigned long long ull;

// ---------------- device scratch (no allocations allowed) ----------------
__device__ float g_gi[(size_t)Tn * 1536 * Bn];   // [t][row(1536)][b]  ~402 MB
__device__ float g_h[2][Bn * Hn];                // ping-pong hidden state
__device__ unsigned g_bar;                       // grid barrier counter

// ---------------- packed fp32x2 helpers (bit-exact 2x FFMA) ----------------
__device__ __forceinline__ void fma2(ull& d, ull a, ull b) {
    asm("fma.rn.f32x2 %0, %1, %2, %0;" : "+l"(d) : "l"(a), "l"(b));
}
__device__ __forceinline__ float hsum2(ull v) {
    float x, y;
    asm("mov.b64 {%0, %1}, %2;" : "=f"(x), "=f"(y) : "l"(v));
    return x + y;
}
__device__ __forceinline__ unsigned ld_acquire_gpu(unsigned* p) {
    unsigned v;
    asm volatile("ld.acquire.gpu.global.u32 %0, [%1];" : "=r"(v) : "l"(p) : "memory");
    return v;
}

// =====================================================================
// Phase 1: GI[t][row][b] = sum_k X[t][b][k] * Wih[row][k] + bih[row]
// Tile: 128 rows x 64 b, K-chunks of 32, k-pair-interleaved smem so the
// 8x4 microtile accumulates with fma.rn.f32x2 (2 MACs/issue).
// =====================================================================
__global__ __launch_bounds__(256, 2) void gemm_ih_kernel(
    const float* __restrict__ X, const float* __restrict__ Wih,
    const float* __restrict__ bih)
{
    __shared__ float Wp[16][256];   // [k2][row*2 + (k even/odd)]
    __shared__ float Xp[16][128];   // [k2][b*2 + (k even/odd)]

    const int tid = threadIdx.x;
    const int rbase = blockIdx.x * 128;   // 12 row tiles
    const int t = blockIdx.y;             // 1024 timesteps

    // one block resets the scan kernel's launch-scoped state (graph-replay safe)
    if (blockIdx.x == 0 && t == 0) {
        if (tid == 0) g_bar = 0u;
        for (int i = tid; i < Bn * Hn; i += 256) g_h[0][i] = 0.f;
    }

    const int tx = tid & 15, ty = tid >> 4;
    const int r0 = ty * 8, b0 = tx * 4;

    ull acc[8][4];
#pragma unroll
    for (int i = 0; i < 8; i++)
#pragma unroll
        for (int j = 0; j < 4; j++) acc[i][j] = 0ull;

    for (int kc = 0; kc < In; kc += 32) {
        // stage W tile (128 rows x 32 k) pair-interleaved
#pragma unroll
        for (int i = tid; i < 1024; i += 256) {
            int r = i >> 3, kq = i & 7;
            float4 v = *(const float4*)&Wih[(size_t)(rbase + r) * In + kc + kq * 4];
            *(float2*)&Wp[kq * 2][r * 2]     = make_float2(v.x, v.y);
            *(float2*)&Wp[kq * 2 + 1][r * 2] = make_float2(v.z, v.w);
        }
        // stage X tile (64 b x 32 k)
#pragma unroll
        for (int i = tid; i < 512; i += 256) {
            int bb = i >> 3, kq = i & 7;
            float4 v = *(const float4*)&X[((size_t)t * Bn + bb) * In + kc + kq * 4];
            *(float2*)&Xp[kq * 2][bb * 2]     = make_float2(v.x, v.y);
            *(float2*)&Xp[kq * 2 + 1][bb * 2] = make_float2(v.z, v.w);
        }
        __syncthreads();

#pragma unroll
        for (int k2 = 0; k2 < 16; k2++) {
            ull w[8], x[4];
            ulonglong2 tmp;
            tmp = *(const ulonglong2*)&Wp[k2][(r0 + 0) * 2]; w[0] = tmp.x; w[1] = tmp.y;
            tmp = *(const ulonglong2*)&Wp[k2][(r0 + 2) * 2]; w[2] = tmp.x; w[3] = tmp.y;
            tmp = *(const ulonglong2*)&Wp[k2][(r0 + 4) * 2]; w[4] = tmp.x; w[5] = tmp.y;
            tmp = *(const ulonglong2*)&Wp[k2][(r0 + 6) * 2]; w[6] = tmp.x; w[7] = tmp.y;
            tmp = *(const ulonglong2*)&Xp[k2][(b0 + 0) * 2]; x[0] = tmp.x; x[1] = tmp.y;
            tmp = *(const ulonglong2*)&Xp[k2][(b0 + 2) * 2]; x[2] = tmp.x; x[3] = tmp.y;
#pragma unroll
            for (int i = 0; i < 8; i++)
#pragma unroll
                for (int j = 0; j < 4; j++)
                    fma2(acc[i][j], w[i], x[j]);
        }
        __syncthreads();
    }

#pragma unroll
    for (int i = 0; i < 8; i++) {
        float bias = bih[rbase + r0 + i];
        float4 o;
        o.x = hsum2(acc[i][0]) + bias;
        o.y = hsum2(acc[i][1]) + bias;
        o.z = hsum2(acc[i][2]) + bias;
        o.w = hsum2(acc[i][3]) + bias;
        *(float4*)&g_gi[((size_t)t * 1536 + rbase + r0 + i) * Bn + b0] = o;
    }
}

// =====================================================================
// Phase 2: persistent sequential scan. 128 blocks x 256 threads.
// Block owns hidden units j in [4*blk, 4*blk+4); its 12 W_hh rows live in
// smem for the whole kernel. Per step: issue gi/pad loads (latency hidden
// under the FMAs), stage h (L2, .cg), 3 dots per thread via f32x2, gates,
// write h_new / outputs, grid barrier.
// =====================================================================
__global__ __launch_bounds__(256, 1) void gru_scan_kernel(
    const float* __restrict__ pad, const float* __restrict__ Whh,
    const float* __restrict__ bhh, float* __restrict__ out)
{
    extern __shared__ float sm[];
    float* W_s  = sm;                    // [12][512]  (g*4+jloc rows)
    float* h_s  = sm + 12 * Hn;          // [64][HPAD]
    float* hn_s = h_s + Bn * HPAD;       // [64][4]

    const int tid = threadIdx.x;
    const int jj = tid >> 6;             // 0..3 (warp-uniform)
    const int b  = tid & 63;
    const int blk = blockIdx.x;
    const int j = blk * JB + jj;

    // load this block's 12 W_hh rows once
    for (int i = tid; i < 12 * (Hn / 4); i += 256) {
        int row = i >> 7;                // 0..11
        int kq  = i & 127;
        int g = row >> 2, jloc = row & 3;
        float4 v = *(const float4*)&Whh[(size_t)(g * Hn + blk * JB + jloc) * Hn + kq * 4];
        *(float4*)&W_s[row * Hn + kq * 4] = v;
    }
    const float bhr = bhh[j], bhz = bhh[Hn + j], bhn = bhh[2 * Hn + j];
    __syncthreads();

    const float* wr = &W_s[(0 * JB + jj) * Hn];
    const float* wz = &W_s[(1 * JB + jj) * Hn];
    const float* wn = &W_s[(2 * JB + jj) * Hn];
    const float* hrow = &h_s[b * HPAD];
    const unsigned nb = gridDim.x;
    const size_t states_off = (size_t)Bn * Tn * Hn;

    for (int t = 0; t < Tn; t++) {
        // issue gate-input loads FIRST: their DRAM/L2 latency hides under
        // the h-staging + 3072 FMA cycles below
        const size_t gib = (size_t)t * 1536;
        float ir  = __ldg(&g_gi[(gib + j) * Bn + b]);
        float iz  = __ldg(&g_gi[(gib + Hn + j) * Bn + b]);
        float in_ = __ldg(&g_gi[(gib + 2 * Hn + j) * Bn + b]);
        float p   = __ldg(&pad[t * Bn + b]);

        // stage h[t] from L2 (bypass L1: remote SMs wrote it)
        const float* hsrc = g_h[t & 1];
        for (int i = tid; i < Bn * (Hn / 4); i += 256) {
            int bb = i >> 7, kq = i & 127;
            float4 v = __ldcg((const float4*)&hsrc[bb * Hn + kq * 4]);
            *(float4*)&h_s[bb * HPAD + kq * 4] = v;
        }
        __syncthreads();

        ull ar0 = 0, ar1 = 0, az0 = 0, az1 = 0, an0 = 0, an1 = 0;
#pragma unroll 8
        for (int k = 0; k < Hn; k += 8) {
            ulonglong2 h0 = *(const ulonglong2*)&hrow[k];
            ulonglong2 h1 = *(const ulonglong2*)&hrow[k + 4];
            ulonglong2 w0, w1;
            w0 = *(const ulonglong2*)&wr[k]; w1 = *(const ulonglong2*)&wr[k + 4];
            fma2(ar0, h0.x, w0.x); fma2(ar1, h0.y, w0.y);
            fma2(ar0, h1.x, w1.x); fma2(ar1, h1.y, w1.y);
            w0 = *(const ulonglong2*)&wz[k]; w1 = *(const ulonglong2*)&wz[k + 4];
            fma2(az0, h0.x, w0.x); fma2(az1, h0.y, w0.y);
            fma2(az0, h1.x, w1.x); fma2(az1, h1.y, w1.y);
            w0 = *(const ulonglong2*)&wn[k]; w1 = *(const ulonglong2*)&wn[k + 4];
            fma2(an0, h0.x, w0.x); fma2(an1, h0.y, w0.y);
            fma2(an0, h1.x, w1.x); fma2(an1, h1.y, w1.y);
        }
        float hr = hsum2(ar0) + hsum2(ar1) + bhr;
        float hz = hsum2(az0) + hsum2(az1) + bhz;
        float hv = hsum2(an0) + hsum2(an1) + bhn;

        float r = 1.f / (1.f + __expf(-(ir + hr)));
        float z = 1.f / (1.f + __expf(-(iz + hz)));
        float narg = in_ + r * hv;
        float n = 1.f - 2.f / (1.f + __expf(2.f * narg));   // tanh, saturation-safe
        float hold = hrow[j];
        float hc = (1.f - z) * n + z * hold;
        float hnew = p * hold + (1.f - p) * hc;

        hn_s[b * JB + jj] = hnew;
        __syncthreads();

        if (tid < Bn) {
            float4 v = *(float4*)&hn_s[tid * JB];
            __stcg((float4*)&g_h[(t + 1) & 1][tid * Hn + blk * JB], v);
            size_t o = ((size_t)tid * Tn + t) * Hn + blk * JB;   // outputs [B][T][H]
            *(float4*)&out[o] = v;
            *(float4*)&out[states_off + o] = v;                  // states == outputs
        }

        // grid barrier (all 128 blocks co-resident: 1 block/SM, 128 <= 148 SMs)
        __threadfence();
        __syncthreads();
        if (tid == 0) {
            atomicAdd(&g_bar, 1u);
            const unsigned target = (unsigned)(t + 1) * nb;
            unsigned v = ld_acquire_gpu(&g_bar);
            while (v < target) {
                __nanosleep(64);
                v = ld_acquire_gpu(&g_bar);
            }
        }
        __syncthreads();
    }
}

// =====================================================================
extern "C" void kernel_launch(void* const* d_in, const int* in_sizes, int n_in,
                              void* d_out, int out_size) {
    const float* X   = (const float*)d_in[0];   // [T,B,I]
    const float* pad = (const float*)d_in[1];   // [T,B,1]
    const float* Wih = (const float*)d_in[2];   // [3H,I]
    const float* Whh = (const float*)d_in[3];   // [3H,H]
    const float* bih = (const float*)d_in[4];   // [3H]
    const float* bhh = (const float*)d_in[5];   // [3H]
    float* out = (float*)d_out;                 // [B,T,H] outputs ++ [B,T,H] states

    dim3 g1(12, Tn);
    gemm_ih_kernel<<<g1, 256>>>(X, Wih, bih);

    const int smem_bytes = (12 * Hn + Bn * HPAD + Bn * JB) * (int)sizeof(float); // 157,696
    cudaFuncSetAttribute(gru_scan_kernel,
                         cudaFuncAttributeMaxDynamicSharedMemorySize, smem_bytes);
    gru_scan_kernel<<<NBLK, 256, smem_bytes>>>(pad, Whh, bhh, out);
}

// round 3
// speedup vs baseline: 1.2814x; 1.2814x over previous
#include <cuda_runtime.h>
#include <cstdint>
#include <cstddef>

// GRU: T=1024, B=64, I=512, H=512
#define Tn 1024
#define Bn 64
#define In 512
#define Hn 512
#define JB 4          // hidden units per block (scan)
#define HPAD 516      // padded h row: lane stride 516 mod 32 = 4 -> 4-phase (BW floor)
#define NBLK 128      // scan blocks (<= #SMs, all co-resident)

typedef unsigned long long ull;

// ---------------- device scratch (no allocations allowed) ----------------
__device__ float g_gi[(size_t)Tn * 1536 * Bn];   // [t][row(1536)][b]  ~402 MB
__device__ float g_h[2][Bn * Hn];                // ping-pong hidden state
__device__ unsigned g_bar;                       // grid barrier counter

// ---------------- packed fp32x2 helpers (bit-exact 2x FFMA) ----------------
__device__ __forceinline__ void fma2(ull& d, ull a, ull b) {
    asm("fma.rn.f32x2 %0, %1, %2, %0;" : "+l"(d) : "l"(a), "l"(b));
}
__device__ __forceinline__ float hsum2(ull v) {
    float x, y;
    asm("mov.b64 {%0, %1}, %2;" : "=f"(x), "=f"(y) : "l"(v));
    return x + y;
}
__device__ __forceinline__ unsigned ld_acquire_gpu(unsigned* p) {
    unsigned v;
    asm volatile("ld.acquire.gpu.global.u32 %0, [%1];" : "=r"(v) : "l"(p) : "memory");
    return v;
}
__device__ __forceinline__ void red_add_release_gpu(unsigned* p, unsigned v) {
    asm volatile("red.add.release.gpu.global.u32 [%0], %1;" :: "l"(p), "r"(v) : "memory");
}

// =====================================================================
// Phase 1: GI[t][row][b] = sum_k X[t][b][k] * Wih[row][k] + bih[row]
// Tile: 128 rows x 64 b, K-chunks of 32, k-pair-interleaved smem so the
// 8x4 microtile accumulates with fma.rn.f32x2 (2 MACs/issue).
// =====================================================================
__global__ __launch_bounds__(256, 2) void gemm_ih_kernel(
    const float* __restrict__ X, const float* __restrict__ Wih,
    const float* __restrict__ bih)
{
    __shared__ float Wp[16][256];   // [k2][row*2 + (k even/odd)]
    __shared__ float Xp[16][128];   // [k2][b*2 + (k even/odd)]

    const int tid = threadIdx.x;
    const int rbase = blockIdx.x * 128;   // 12 row tiles
    const int t = blockIdx.y;             // 1024 timesteps

    // one block resets the scan kernel's launch-scoped state (graph-replay safe)
    if (blockIdx.x == 0 && t == 0) {
        if (tid == 0) g_bar = 0u;
        for (int i = tid; i < Bn * Hn; i += 256) g_h[0][i] = 0.f;
    }

    const int tx = tid & 15, ty = tid >> 4;
    const int r0 = ty * 8, b0 = tx * 4;

    ull acc[8][4];
#pragma unroll
    for (int i = 0; i < 8; i++)
#pragma unroll
        for (int j = 0; j < 4; j++) acc[i][j] = 0ull;

    for (int kc = 0; kc < In; kc += 32) {
#pragma unroll
        for (int i = tid; i < 1024; i += 256) {
            int r = i >> 3, kq = i & 7;
            float4 v = *(const float4*)&Wih[(size_t)(rbase + r) * In + kc + kq * 4];
            *(float2*)&Wp[kq * 2][r * 2]     = make_float2(v.x, v.y);
            *(float2*)&Wp[kq * 2 + 1][r * 2] = make_float2(v.z, v.w);
        }
#pragma unroll
        for (int i = tid; i < 512; i += 256) {
            int bb = i >> 3, kq = i & 7;
            float4 v = *(const float4*)&X[((size_t)t * Bn + bb) * In + kc + kq * 4];
            *(float2*)&Xp[kq * 2][bb * 2]     = make_float2(v.x, v.y);
            *(float2*)&Xp[kq * 2 + 1][bb * 2] = make_float2(v.z, v.w);
        }
        __syncthreads();

#pragma unroll
        for (int k2 = 0; k2 < 16; k2++) {
            ull w[8], x[4];
            ulonglong2 tmp;
            tmp = *(const ulonglong2*)&Wp[k2][(r0 + 0) * 2]; w[0] = tmp.x; w[1] = tmp.y;
            tmp = *(const ulonglong2*)&Wp[k2][(r0 + 2) * 2]; w[2] = tmp.x; w[3] = tmp.y;
            tmp = *(const ulonglong2*)&Wp[k2][(r0 + 4) * 2]; w[4] = tmp.x; w[5] = tmp.y;
            tmp = *(const ulonglong2*)&Wp[k2][(r0 + 6) * 2]; w[6] = tmp.x; w[7] = tmp.y;
            tmp = *(const ulonglong2*)&Xp[k2][(b0 + 0) * 2]; x[0] = tmp.x; x[1] = tmp.y;
            tmp = *(const ulonglong2*)&Xp[k2][(b0 + 2) * 2]; x[2] = tmp.x; x[3] = tmp.y;
#pragma unroll
            for (int i = 0; i < 8; i++)
#pragma unroll
                for (int j = 0; j < 4; j++)
                    fma2(acc[i][j], w[i], x[j]);
        }
        __syncthreads();
    }

#pragma unroll
    for (int i = 0; i < 8; i++) {
        float bias = bih[rbase + r0 + i];
        float4 o;
        o.x = hsum2(acc[i][0]) + bias;
        o.y = hsum2(acc[i][1]) + bias;
        o.z = hsum2(acc[i][2]) + bias;
        o.w = hsum2(acc[i][3]) + bias;
        *(float4*)&g_gi[((size_t)t * 1536 + rbase + r0 + i) * Bn + b0] = o;
    }
}

// =====================================================================
// Phase 2: persistent sequential scan. 128 blocks x 256 threads.
// Dot phase re-tiled k-split: warp kq (0..7) owns k in [kq*64, kq*64+64);
// lane bp owns batches {bp, bp+32}; each thread accumulates ALL 12
// (gate,j) rows over its k-slice -> h smem read exactly once per SM,
// each w LDS.128 (broadcast) feeds 4 fma2. FMA-bound (~3072 cyc/SM/step).
// kq-partials reduced through smem; gates computed by thread (jj,b).
// =====================================================================
__global__ __launch_bounds__(256, 1) void gru_scan_kernel(
    const float* __restrict__ pad, const float* __restrict__ Whh,
    const float* __restrict__ bhh, float* __restrict__ out)
{
    extern __shared__ float sm[];
    float* W_s  = sm;                      // [12][512]  rows: g*4+jloc
    float* h_s  = W_s + 12 * Hn;           // [64][HPAD]
    float* p_s  = h_s + Bn * HPAD;         // [12][8][64] kq-partials
    float* hn_s = p_s + 12 * 8 * 64;       // [64][4]

    const int tid = threadIdx.x;
    const int blk = blockIdx.x;

    // gate-phase ids
    const int jj = tid >> 6;               // 0..3
    const int bg = tid & 63;
    const int j  = blk * JB + jj;

    // dot-phase ids
    const int kq = tid >> 5;               // warp id 0..7 = k-slice
    const int bp = tid & 31;

    // load this block's 12 W_hh rows once
    for (int i = tid; i < 12 * (Hn / 4); i += 256) {
        int row = i >> 7;                  // 0..11
        int kk  = i & 127;
        int g = row >> 2, jloc = row & 3;
        float4 v = *(const float4*)&Whh[(size_t)(g * Hn + blk * JB + jloc) * Hn + kk * 4];
        *(float4*)&W_s[row * Hn + kk * 4] = v;
    }
    const float bhr = bhh[j], bhz = bhh[Hn + j], bhn = bhh[2 * Hn + j];
    __syncthreads();

    const float* hp1 = &h_s[bp * HPAD + kq * 64];
    const float* hp2 = &h_s[(bp + 32) * HPAD + kq * 64];
    const float* wq  = &W_s[kq * 64];      // row r slice at wq + r*Hn
    const size_t states_off = (size_t)Bn * Tn * Hn;

    for (int t = 0; t < Tn; t++) {
        // gate-input loads first: DRAM latency hides under staging + FMAs
        const size_t gib = (size_t)t * 1536;
        float ir  = __ldg(&g_gi[(gib + j) * Bn + bg]);
        float iz  = __ldg(&g_gi[(gib + Hn + j) * Bn + bg]);
        float in_ = __ldg(&g_gi[(gib + 2 * Hn + j) * Bn + bg]);
        float p   = __ldg(&pad[t * Bn + bg]);

        // stage h[t] from L2 (bypass L1: remote SMs wrote it)
        const float* hsrc = g_h[t & 1];
        for (int i = tid; i < Bn * (Hn / 4); i += 256) {
            int bb = i >> 7, kk = i & 127;
            float4 v = __ldcg((const float4*)&hsrc[bb * Hn + kk * 4]);
            *(float4*)&h_s[bb * HPAD + kk * 4] = v;
        }
        __syncthreads();

        // ---- dot phase: 12 rows x 2 batches over 64 k ----
        ull acc[12][2];
#pragma unroll
        for (int r = 0; r < 12; r++) { acc[r][0] = 0ull; acc[r][1] = 0ull; }

#pragma unroll
        for (int c = 0; c < 16; c++) {     // 4-k chunks
            ulonglong2 h1 = *(const ulonglong2*)&hp1[c * 4];
            ulonglong2 h2 = *(const ulonglong2*)&hp2[c * 4];
#pragma unroll
            for (int r = 0; r < 12; r++) {
                ulonglong2 w = *(const ulonglong2*)&wq[r * Hn + c * 4];
                fma2(acc[r][0], h1.x, w.x); fma2(acc[r][0], h1.y, w.y);
                fma2(acc[r][1], h2.x, w.x); fma2(acc[r][1], h2.y, w.y);
            }
        }
#pragma unroll
        for (int r = 0; r < 12; r++) {
            p_s[r * 512 + kq * 64 + bp]      = hsum2(acc[r][0]);
            p_s[r * 512 + kq * 64 + 32 + bp] = hsum2(acc[r][1]);
        }
        __syncthreads();

        // ---- reduce + gates: thread (jj, bg) ----
        float hr = bhr, hz = bhz, hv = bhn;
#pragma unroll
        for (int q = 0; q < 8; q++) {
            hr += p_s[(jj)     * 512 + q * 64 + bg];
            hz += p_s[(4 + jj) * 512 + q * 64 + bg];
            hv += p_s[(8 + jj) * 512 + q * 64 + bg];
        }
        float r = 1.f / (1.f + __expf(-(ir + hr)));
        float z = 1.f / (1.f + __expf(-(iz + hz)));
        float narg = in_ + r * hv;
        float n = 1.f - 2.f / (1.f + __expf(2.f * narg));   // tanh, saturation-safe
        float hold = h_s[bg * HPAD + j];
        float hc = (1.f - z) * n + z * hold;
        float hnew = p * hold + (1.f - p) * hc;

        hn_s[bg * JB + jj] = hnew;
        __syncthreads();

        // critical-path publish: next-step h only
        if (tid < Bn) {
            float4 v = *(float4*)&hn_s[tid * JB];
            __stcg((float4*)&g_h[(t + 1) & 1][tid * Hn + blk * JB], v);
        }
        __syncthreads();                   // g_h stores ordered before release
        if (tid == 0) red_add_release_gpu(&g_bar, 1u);

        // off-critical-path: output stores overlap the barrier wait
        if (tid < Bn) {
            float4 v = *(float4*)&hn_s[tid * JB];
            size_t o = ((size_t)tid * Tn + t) * Hn + blk * JB;   // [B][T][H]
            *(float4*)&out[o] = v;
            *(float4*)&out[states_off + o] = v;                  // states == outputs
        }

        if (tid == 0) {
            const unsigned target = (unsigned)(t + 1) * (unsigned)NBLK;
            while (ld_acquire_gpu(&g_bar) < target) { }
        }
        __syncthreads();
    }
}

// =====================================================================
extern "C" void kernel_launch(void* const* d_in, const int* in_sizes, int n_in,
                              void* d_out, int out_size) {
    const float* X   = (const float*)d_in[0];   // [T,B,I]
    const float* pad = (const float*)d_in[1];   // [T,B,1]
    const float* Wih = (const float*)d_in[2];   // [3H,I]
    const float* Whh = (const float*)d_in[3];   // [3H,H]
    const float* bih = (const float*)d_in[4];   // [3H]
    const float* bhh = (const float*)d_in[5];   // [3H]
    float* out = (float*)d_out;                 // [B,T,H] outputs ++ [B,T,H] states

    dim3 g1(12, Tn);
    gemm_ih_kernel<<<g1, 256>>>(X, Wih, bih);

    const int smem_bytes = (12 * Hn + Bn * HPAD + 12 * 8 * 64 + Bn * JB) * (int)sizeof(float);
    cudaFuncSetAttribute(gru_scan_kernel,
                         cudaFuncAttributeMaxDynamicSharedMemorySize, smem_bytes);
    gru_scan_kernel<<<NBLK, 256, smem_bytes>>>(pad, Whh, bhh, out);
}